// round 13
// baseline (speedup 1.0000x reference)
#include <cuda_runtime.h>
#include <cuda_bf16.h>

// out[b] = sum_k x[b,k] * |W[k]| * fc1_w[k] + fc1_b
// B=32, K = T*P = 4,000,000
#define NBATCH  32
#define TP      4000000
#define NVEC    (TP / 4)      // 1,000,000 float4 per batch row
#define GROUPS  27            // grid 864 ~= 148 SM * 6 CTA (R9's optimum)
#define THREADS 256
#define STRIDE  (GROUPS * THREADS)   // 6912 float4 per sweep
#define NIT     ((NVEC + STRIDE - 1) / STRIDE)   // 145 pipeline iterations
#define STAGES  4

typedef unsigned int u32;

__global__ void init_out_kernel(const float* __restrict__ fc1_b,
                                float* __restrict__ out) {
    out[threadIdx.x] = fc1_b[0];
}

__device__ __forceinline__ void cpa16(u32 saddr, const void* gaddr) {
    asm volatile("cp.async.cg.shared.global [%0], [%1], 16;"
                 :: "r"(saddr), "l"(gaddr) : "memory");
}
__device__ __forceinline__ void cpa_commit() {
    asm volatile("cp.async.commit_group;" ::: "memory");
}
__device__ __forceinline__ void cpa_wait() {
    asm volatile("cp.async.wait_group %0;" :: "n"(STAGES - 1) : "memory");
}

__global__ __launch_bounds__(THREADS, 6)   // 6 CTAs/SM: the proven optimum
void dot_kernel(const float4* __restrict__ x,
                const float4* __restrict__ W,
                const float4* __restrict__ F,
                float* __restrict__ out) {
    // x staging: 4 stages x 256 threads x 16B = 16 KB. Each thread only ever
    // touches its own slot -> zero barriers; cp.async.wait_group orders it.
    __shared__ float4 xs[STAGES][THREADS];

    const int b   = blockIdx.x & (NBATCH - 1);   // batch (fastest-varying)
    const int g   = blockIdx.x >> 5;             // column group 0..26
    const int tid = threadIdx.x;
    const int j0  = g * THREADS + tid;

    const float4* __restrict__ xb = x + (size_t)b * NVEC;

    u32 slot[STAGES];
#pragma unroll
    for (int s = 0; s < STAGES; s++)
        slot[s] = (u32)__cvta_generic_to_shared(&xs[s][tid]);

    // ---- pipeline prologue: fill STAGES groups ----
#pragma unroll
    for (int s = 0; s < STAGES; s++) {
        int jp = j0 + s * STRIDE;
        if (jp < NVEC) cpa16(slot[s], &xb[jp]);
        cpa_commit();
    }

    float a0 = 0.f, a1 = 0.f, a2 = 0.f, a3 = 0.f;

#pragma unroll 1
    for (int it = 0; it < NIT; it++) {
        const int stage = it & (STAGES - 1);
        const int jc = j0 + it * STRIDE;

        cpa_wait();   // group 'it' complete -> xs[stage][tid] valid

        if (jc < NVEC) {
            float4 xv = xs[stage][tid];          // LDS.128
            float4 w  = __ldg(&W[jc]);           // L2-resident
            float4 f  = __ldg(&F[jc]);
            a0 = fmaf(xv.x, fabsf(w.x) * f.x, a0);
            a1 = fmaf(xv.y, fabsf(w.y) * f.y, a1);
            a2 = fmaf(xv.z, fabsf(w.z) * f.z, a2);
            a3 = fmaf(xv.w, fabsf(w.w) * f.w, a3);
        }

        // refill this stage for iteration it+STAGES
        int jn = j0 + (it + STAGES) * STRIDE;
        if (jn < NVEC) cpa16(slot[stage], &xb[jn]);
        cpa_commit();   // commit even if empty: keeps group counting uniform
    }

    float v = (a0 + a1) + (a2 + a3);

    // ---- block reduction: warp shfl -> smem -> single atomic ----
    __shared__ float sred[THREADS / 32];
    const int lane = tid & 31;
    const int wrp  = tid >> 5;

#pragma unroll
    for (int off = 16; off; off >>= 1)
        v += __shfl_xor_sync(0xffffffffu, v, off);
    if (lane == 0) sred[wrp] = v;
    __syncthreads();

    if (wrp == 0) {
        float s = (lane < THREADS / 32) ? sred[lane] : 0.f;
#pragma unroll
        for (int off = 4; off; off >>= 1)
            s += __shfl_xor_sync(0xffffffffu, s, off);
        if (lane == 0) atomicAdd(&out[b], s);
    }
}

extern "C" void kernel_launch(void* const* d_in, const int* in_sizes, int n_in,
                              void* d_out, int out_size) {
    const float4* x  = (const float4*)d_in[0];  // [32, 4M]
    const float4* W  = (const float4*)d_in[1];  // [4M]
    const float4* F  = (const float4*)d_in[2];  // fc1_w [4M]
    const float*  bb = (const float*)d_in[3];   // fc1_b [1]
    float* out = (float*)d_out;                 // [32]

    (void)in_sizes; (void)n_in; (void)out_size;

    init_out_kernel<<<1, NBATCH>>>(bb, out);
    dot_kernel<<<NBATCH * GROUPS, THREADS>>>(x, W, F, out);
}

// round 14
// speedup vs baseline: 1.4263x; 1.4263x over previous
#include <cuda_runtime.h>
#include <cuda_bf16.h>

// out[b] = sum_k x[b,k] * |W[k]| * fc1_w[k] + fc1_b
// B=32, K = T*P = 4,000,000
#define NBATCH  32
#define TP      4000000
#define NVEC    (TP / 4)      // 1,000,000 float4 per batch row
#define GROUPS  27            // column groups -> grid 864 ~= 148 SM * 6 CTA
#define THREADS 256
#define STRIDE  (GROUPS * THREADS)   // 6912 float4 per sweep

__global__ void init_out_kernel(const float* __restrict__ fc1_b,
                                float* __restrict__ out) {
    out[threadIdx.x] = fc1_b[0];
}

__global__ __launch_bounds__(THREADS, 6)   // cap regs at 42 -> 6 CTAs/SM
void dot_kernel(const float4* __restrict__ x,
                const float4* __restrict__ W,
                const float4* __restrict__ F,
                float* __restrict__ out) {
    const int b   = blockIdx.x & (NBATCH - 1);   // batch (fastest-varying)
    const int g   = blockIdx.x >> 5;             // column group 0..26
    const int tid = threadIdx.x;

    const float4* __restrict__ xb = x + (size_t)b * NVEC;

    float a0 = 0.f, a1 = 0.f, a2 = 0.f, a3 = 0.f;

    // unroll 2 (not 4): keeps live float4 count at 6 -> ~40 regs, no spills
#pragma unroll 2
    for (int j = g * THREADS + tid; j < NVEC; j += STRIDE) {
        // x: read-once stream -> evict-first so it can't thrash W/F in L2
        float4 xv = __ldcs(&xb[j]);
        // W/F: shared across the 32 co-resident batch-blocks -> L2 hits
        float4 w = __ldg(&W[j]);
        float4 f = __ldg(&F[j]);
        a0 = fmaf(xv.x, fabsf(w.x) * f.x, a0);
        a1 = fmaf(xv.y, fabsf(w.y) * f.y, a1);
        a2 = fmaf(xv.z, fabsf(w.z) * f.z, a2);
        a3 = fmaf(xv.w, fabsf(w.w) * f.w, a3);
    }

    float v = (a0 + a1) + (a2 + a3);

    // ---- block reduction: warp shfl -> smem -> single atomic ----
    __shared__ float sred[THREADS / 32];
    const int lane = tid & 31;
    const int wrp  = tid >> 5;

#pragma unroll
    for (int off = 16; off; off >>= 1)
        v += __shfl_xor_sync(0xffffffffu, v, off);
    if (lane == 0) sred[wrp] = v;
    __syncthreads();

    if (wrp == 0) {
        float s = (lane < THREADS / 32) ? sred[lane] : 0.f;
#pragma unroll
        for (int off = 4; off; off >>= 1)
            s += __shfl_xor_sync(0xffffffffu, s, off);
        if (lane == 0) atomicAdd(&out[b], s);
    }
}

extern "C" void kernel_launch(void* const* d_in, const int* in_sizes, int n_in,
                              void* d_out, int out_size) {
    const float4* x  = (const float4*)d_in[0];  // [32, 4M]
    const float4* W  = (const float4*)d_in[1];  // [4M]
    const float4* F  = (const float4*)d_in[2];  // fc1_w [4M]
    const float*  bb = (const float*)d_in[3];   // fc1_b [1]
    float* out = (float*)d_out;                 // [32]

    (void)in_sizes; (void)n_in; (void)out_size;

    init_out_kernel<<<1, NBATCH>>>(bb, out);
    dot_kernel<<<NBATCH * GROUPS, THREADS>>>(x, W, F, out);
}

// round 15
// speedup vs baseline: 1.4291x; 1.0020x over previous
#include <cuda_runtime.h>
#include <cuda_bf16.h>

// out[b] = sum_k x[b,k] * |W[k]| * fc1_w[k] + fc1_b
// B=32, K = T*P = 4,000,000
#define NBATCH  32
#define TP      4000000
#define NVEC    (TP / 4)      // 1,000,000 float4 per batch row
#define GROUPS  27            // column groups -> grid 864 ~= 148 SM * 6 CTA
#define THREADS 256
#define STRIDE  (GROUPS * THREADS)   // 6912 float4 per sweep

__global__ void init_out_kernel(const float* __restrict__ fc1_b,
                                float* __restrict__ out) {
    out[threadIdx.x] = fc1_b[0];
}

__global__ __launch_bounds__(THREADS, 6)   // cap regs at 42 -> 6 CTAs/SM
void dot_kernel(const float4* __restrict__ x,
                const float4* __restrict__ W,
                const float4* __restrict__ F,
                float* __restrict__ out) {
    const int b   = blockIdx.x & (NBATCH - 1);   // batch (fastest-varying)
    const int g   = blockIdx.x >> 5;             // column group 0..26
    const int tid = threadIdx.x;

    const float4* __restrict__ xb = x + (size_t)b * NVEC;

    float a0 = 0.f, a1 = 0.f, a2 = 0.f, a3 = 0.f;

    // unroll 2 (not 4): keeps live float4 count at 6 -> ~40 regs, no spills
#pragma unroll 2
    for (int j = g * THREADS + tid; j < NVEC; j += STRIDE) {
        // x: read-once stream -> evict-first so it can't thrash W/F in L2
        float4 xv = __ldcs(&xb[j]);
        // W/F: shared across the 32 co-resident batch-blocks -> L2 hits
        float4 w = __ldg(&W[j]);
        float4 f = __ldg(&F[j]);
        a0 = fmaf(xv.x, fabsf(w.x) * f.x, a0);
        a1 = fmaf(xv.y, fabsf(w.y) * f.y, a1);
        a2 = fmaf(xv.z, fabsf(w.z) * f.z, a2);
        a3 = fmaf(xv.w, fabsf(w.w) * f.w, a3);
    }

    float v = (a0 + a1) + (a2 + a3);

    // ---- block reduction: warp shfl -> smem -> single atomic ----
    __shared__ float sred[THREADS / 32];
    const int lane = tid & 31;
    const int wrp  = tid >> 5;

#pragma unroll
    for (int off = 16; off; off >>= 1)
        v += __shfl_xor_sync(0xffffffffu, v, off);
    if (lane == 0) sred[wrp] = v;
    __syncthreads();

    if (wrp == 0) {
        float s = (lane < THREADS / 32) ? sred[lane] : 0.f;
#pragma unroll
        for (int off = 4; off; off >>= 1)
            s += __shfl_xor_sync(0xffffffffu, s, off);
        if (lane == 0) atomicAdd(&out[b], s);
    }
}

extern "C" void kernel_launch(void* const* d_in, const int* in_sizes, int n_in,
                              void* d_out, int out_size) {
    const float4* x  = (const float4*)d_in[0];  // [32, 4M]
    const float4* W  = (const float4*)d_in[1];  // [4M]
    const float4* F  = (const float4*)d_in[2];  // fc1_w [4M]
    const float*  bb = (const float*)d_in[3];   // fc1_b [1]
    float* out = (float*)d_out;                 // [32]

    (void)in_sizes; (void)n_in; (void)out_size;

    init_out_kernel<<<1, NBATCH>>>(bb, out);
    dot_kernel<<<NBATCH * GROUPS, THREADS>>>(x, W, F, out);
}